// round 2
// baseline (speedup 1.0000x reference)
#include <cuda_runtime.h>
#include <cstdint>

#define N_NODES 100000
#define HIDDEN  128
#define NPB     64   // nodes per block in GEMM kernel

// Scratch (device globals — allocation-free rule)
__device__ __align__(16) float g_S [(size_t)N_NODES * HIDDEN];
__device__ __align__(16) float g_I [(size_t)N_NODES * HIDDEN];
__device__ __align__(16) float g_AI[(size_t)N_NODES * HIDDEN];

// Packed fp32x2 FMA (Blackwell): 2x FFMA throughput vs scalar FFMA
__device__ __forceinline__ unsigned long long ffma2(unsigned long long a,
                                                    unsigned long long b,
                                                    unsigned long long c) {
    unsigned long long d;
    asm("fma.rn.f32x2 %0, %1, %2, %3;" : "=l"(d) : "l"(a), "l"(b), "l"(c));
    return d;
}

// ---------------------------------------------------------------------------
// K1: sigmoid GEMM for s in {0,1}:  out[n,o] = sigmoid(sum_h x[s,n,h]*W[o,h] + b[o])
//     Writes g_S, g_I. Also fuses: zero g_AI, out[2] = gamma*I, out[3] = 0.
// ---------------------------------------------------------------------------
__global__ __launch_bounds__(256, 2) void k_gemm(
    const float* __restrict__ x, const float* __restrict__ W,
    const float* __restrict__ b, float* __restrict__ out)
{
    extern __shared__ float sh[];
    float* Ws   = sh;                    // 128*129 floats
    float* xs   = sh + 128 * 129;        // 128*66  floats
    float* sgam = xs + 128 * 66;         // 64 floats

    const int tid  = threadIdx.x;
    const int o    = tid & 127;
    const int g    = tid >> 7;
    const int base = blockIdx.x * NPB;
    const int nn   = min(NPB, N_NODES - base);

    // Load W transposed: Ws[h*129 + o] = W[o*128 + h]
    for (int idx = tid; idx < HIDDEN * HIDDEN; idx += 256) {
        Ws[(idx & 127) * 129 + (idx >> 7)] = W[idx];
    }
    // gamma = x[3, node, 1]
    if (tid < NPB) {
        sgam[tid] = (tid < nn)
            ? x[((size_t)3 * N_NODES + base + tid) * HIDDEN + 1] : 0.f;
    }
    // Zero this block's slice of g_AI
    {
        const int lim = nn * HIDDEN;
        float* ai = g_AI + (size_t)base * HIDDEN;
        for (int idx = tid; idx < lim; idx += 256) ai[idx] = 0.f;
    }
    const float bias = b[o];
    __syncthreads();

    for (int s = 0; s < 2; ++s) {
        // Load x tile transposed into shared: xs[h*66 + n]
        const float* xsrc = x + ((size_t)s * N_NODES + base) * HIDDEN;
        for (int idx = tid; idx < NPB * HIDDEN; idx += 256) {
            const int n = idx >> 7, h = idx & 127;
            xs[h * 66 + n] = (n < nn) ? xsrc[idx] : 0.f;
        }
        __syncthreads();

        unsigned long long acc[16];
        #pragma unroll
        for (int p = 0; p < 16; ++p) acc[p] = 0ull;

        const int n0 = g * 32;
        #pragma unroll 2
        for (int h = 0; h < HIDDEN; ++h) {
            const float w = Ws[h * 129 + o];
            unsigned long long w2;
            {
                const unsigned wu = __float_as_uint(w);
                asm("mov.b64 %0, {%1,%1};" : "=l"(w2) : "r"(wu));
            }
            const float* xr = &xs[h * 66 + n0];
            #pragma unroll
            for (int p = 0; p < 16; ++p) {
                const unsigned long long xv =
                    *reinterpret_cast<const unsigned long long*>(xr + 2 * p);
                acc[p] = ffma2(xv, w2, acc[p]);  // two FMAs: nodes 2p, 2p+1
            }
        }

        #pragma unroll
        for (int p = 0; p < 16; ++p) {
            const float lo = __uint_as_float((unsigned)(acc[p] & 0xffffffffull));
            const float hi = __uint_as_float((unsigned)(acc[p] >> 32));
            const float v0 = 1.f / (1.f + __expf(-(lo + bias)));
            const float v1 = 1.f / (1.f + __expf(-(hi + bias)));
            const int nA = n0 + 2 * p;
            const int nB = nA + 1;
            if (s == 0) {
                if (nA < nn) g_S[((size_t)(base + nA)) * HIDDEN + o] = v0;
                if (nB < nn) g_S[((size_t)(base + nB)) * HIDDEN + o] = v1;
            } else {
                if (nA < nn) {
                    const size_t off = ((size_t)(base + nA)) * HIDDEN + o;
                    g_I[off] = v0;
                    out[(size_t)2 * N_NODES * HIDDEN + off] = sgam[nA] * v0; // dR
                    out[(size_t)3 * N_NODES * HIDDEN + off] = 0.f;
                }
                if (nB < nn) {
                    const size_t off = ((size_t)(base + nB)) * HIDDEN + o;
                    g_I[off] = v1;
                    out[(size_t)2 * N_NODES * HIDDEN + off] = sgam[nB] * v1; // dR
                    out[(size_t)3 * N_NODES * HIDDEN + off] = 0.f;
                }
            }
        }
        __syncthreads();  // protect xs before s=1 overwrite
    }
}

// ---------------------------------------------------------------------------
// K2: edge scatter. One warp per edge: AI[row, :] += I[col, :]
//     Indices are INT32 (JAX default config downcasts jnp.int64 -> int32).
//     Clamp defensively: identity on valid data, no crash on bad dtype theory.
// ---------------------------------------------------------------------------
__global__ __launch_bounds__(256) void k_edge(
    const int* __restrict__ rows, const int* __restrict__ cols, int n_edges)
{
    const int warp = (blockIdx.x * 256 + threadIdx.x) >> 5;
    if (warp >= n_edges) return;
    const int lane = threadIdx.x & 31;

    int r = rows[warp];
    int c = cols[warp];
    r = min(max(r, 0), N_NODES - 1);
    c = min(max(c, 0), N_NODES - 1);

    const float4 v = reinterpret_cast<const float4*>(g_I + (size_t)c * HIDDEN)[lane];
    float* dst = g_AI + (size_t)r * HIDDEN + lane * 4;
    atomicAdd(dst + 0, v.x);
    atomicAdd(dst + 1, v.y);
    atomicAdd(dst + 2, v.z);
    atomicAdd(dst + 3, v.w);
}

// ---------------------------------------------------------------------------
// K3: finalize.  dS = -beta*AI*S ; dI = -dS - gamma*I (= -dS - out[2])
// ---------------------------------------------------------------------------
__global__ __launch_bounds__(256) void k_final(
    const float* __restrict__ x, float* __restrict__ out)
{
    const size_t i = (size_t)blockIdx.x * 256 + threadIdx.x;  // float4 index
    const size_t total = (size_t)N_NODES * (HIDDEN / 4);
    if (i >= total) return;
    const int node = (int)(i >> 5);

    const float beta = __ldg(&x[((size_t)3 * N_NODES + node) * HIDDEN]);

    const float4 S4 = reinterpret_cast<const float4*>(g_S)[i];
    const float4 A4 = reinterpret_cast<const float4*>(g_AI)[i];
    const float4 G4 = reinterpret_cast<const float4*>(
        out + (size_t)2 * N_NODES * HIDDEN)[i];  // gamma*I

    float4 dS, dI;
    dS.x = -beta * A4.x * S4.x;  dI.x = -dS.x - G4.x;
    dS.y = -beta * A4.y * S4.y;  dI.y = -dS.y - G4.y;
    dS.z = -beta * A4.z * S4.z;  dI.z = -dS.z - G4.z;
    dS.w = -beta * A4.w * S4.w;  dI.w = -dS.w - G4.w;

    reinterpret_cast<float4*>(out)[i] = dS;
    reinterpret_cast<float4*>(out + (size_t)N_NODES * HIDDEN)[i] = dI;
}

// ---------------------------------------------------------------------------
extern "C" void kernel_launch(void* const* d_in, const int* in_sizes, int n_in,
                              void* d_out, int out_size)
{
    const float* x    = (const float*)d_in[0];
    const float* W    = (const float*)d_in[1];
    const float* b    = (const float*)d_in[2];
    const int*   rows = (const int*)d_in[3];
    const int*   cols = (const int*)d_in[4];
    float*       out  = (float*)d_out;

    const int n_edges = in_sizes[3];

    const size_t smem = (size_t)(128 * 129 + 128 * 66 + 64) * sizeof(float);
    cudaFuncSetAttribute(k_gemm, cudaFuncAttributeMaxDynamicSharedMemorySize,
                         (int)smem);

    const int gemm_blocks = (N_NODES + NPB - 1) / NPB;
    k_gemm<<<gemm_blocks, 256, smem>>>(x, W, b, out);

    const int edge_blocks = (n_edges + 7) / 8;   // 8 warps per block
    k_edge<<<edge_blocks, 256>>>(rows, cols, n_edges);

    const int fin_blocks = (N_NODES * (HIDDEN / 4) + 255) / 256;
    k_final<<<fin_blocks, 256>>>(x, out);
}

// round 3
// speedup vs baseline: 3.0450x; 3.0450x over previous
#include <cuda_runtime.h>
#include <cstdint>

#define N_NODES 100000
#define HIDDEN  128
#define NPB     128   // nodes per block in GEMM kernel
#define CAP     48    // per-node edge bin capacity (Poisson mean 16; P(>=48)~1e-10)

// Scratch (device globals — allocation-free rule)
__device__ __align__(16) float g_S  [(size_t)N_NODES * HIDDEN];
__device__ __align__(16) float g_I  [(size_t)N_NODES * HIDDEN];
__device__ int   g_cnt[N_NODES];
__device__ int   g_bin[(size_t)N_NODES * CAP];
__device__ int   g_ovf_cnt;
__device__ int   g_ovf[2 * 1600000];

// Packed fp32x2 FMA (Blackwell): 2x FFMA throughput vs scalar FFMA
__device__ __forceinline__ unsigned long long ffma2(unsigned long long a,
                                                    unsigned long long b,
                                                    unsigned long long c) {
    unsigned long long d;
    asm("fma.rn.f32x2 %0, %1, %2, %3;" : "=l"(d) : "l"(a), "l"(b), "l"(c));
    return d;
}
__device__ __forceinline__ unsigned long long dup2(float w) {
    unsigned long long d;
    const unsigned wu = __float_as_uint(w);
    asm("mov.b64 %0, {%1,%1};" : "=l"(d) : "r"(wu));
    return d;
}
__device__ __forceinline__ float sigmoidf(float v) {
    return 1.f / (1.f + __expf(-v));
}

// ---------------------------------------------------------------------------
// K1: sigmoid GEMM for s in {0,1}. Register tile: 4 outputs x 16 nodes/thread.
//   o_grp = tid&31 -> o0 = 4*o_grp (LDS.128 of Ws row, conflict-free)
//   n_grp = tid>>5 -> 16 nodes = 8 pairs (broadcast LDS.64 from xs)
// Fuses: out[2] = gamma*I, out[3] = 0, zero g_cnt / g_ovf_cnt.
// ---------------------------------------------------------------------------
__global__ __launch_bounds__(256, 1) void k_gemm(
    const float* __restrict__ x, const float* __restrict__ W,
    const float* __restrict__ b, float* __restrict__ out)
{
    extern __shared__ float sh[];
    float* Ws   = sh;                     // 128 x 132 (pitch 132)
    float* xs   = sh + 128 * 132;         // 128 x 130 (pitch 130)
    float* sgam = xs + 128 * 130;         // 128

    const int tid   = threadIdx.x;
    const int o_grp = tid & 31;
    const int o0    = o_grp * 4;
    const int n_grp = tid >> 5;
    const int n0    = n_grp * 16;
    const int base  = blockIdx.x * NPB;
    const int nn    = min(NPB, N_NODES - base);

    // Ws[h*132 + o] = W[o*128 + h]  (4-way bank conflict on store, one-time)
    for (int idx = tid; idx < HIDDEN * HIDDEN; idx += 256) {
        Ws[(idx & 127) * 132 + (idx >> 7)] = W[idx];
    }
    // gamma = x[3, node, 1]; zero per-node edge counters
    if (tid < NPB) {
        const int n = base + tid;
        sgam[tid] = (tid < nn) ? x[((size_t)3 * N_NODES + n) * HIDDEN + 1] : 0.f;
        if (n < N_NODES) g_cnt[n] = 0;
    }
    if (blockIdx.x == 0 && tid == 0) g_ovf_cnt = 0;

    float bias[4];
    #pragma unroll
    for (int oi = 0; oi < 4; ++oi) bias[oi] = b[o0 + oi];
    __syncthreads();

    for (int s = 0; s < 2; ++s) {
        // xs[h*130 + n] = x[s, base+n, h]
        const float* xsrc = x + ((size_t)s * N_NODES + base) * HIDDEN;
        for (int idx = tid; idx < NPB * HIDDEN; idx += 256) {
            const int n = idx >> 7, h = idx & 127;
            xs[h * 130 + n] = (n < nn) ? xsrc[idx] : 0.f;
        }
        __syncthreads();

        unsigned long long acc[4][8];
        #pragma unroll
        for (int oi = 0; oi < 4; ++oi)
            #pragma unroll
            for (int p = 0; p < 8; ++p) acc[oi][p] = 0ull;

        #pragma unroll 2
        for (int h = 0; h < HIDDEN; ++h) {
            const float4 w4 = *reinterpret_cast<const float4*>(&Ws[h * 132 + o0]);
            unsigned long long w2[4];
            w2[0] = dup2(w4.x); w2[1] = dup2(w4.y);
            w2[2] = dup2(w4.z); w2[3] = dup2(w4.w);
            const float* xr = &xs[h * 130 + n0];
            #pragma unroll
            for (int p = 0; p < 8; ++p) {
                const unsigned long long xv =
                    *reinterpret_cast<const unsigned long long*>(xr + 2 * p);
                #pragma unroll
                for (int oi = 0; oi < 4; ++oi)
                    acc[oi][p] = ffma2(xv, w2[oi], acc[oi][p]);
            }
        }

        // Epilogue: per pair p -> nodes nA = n0+2p, nB = nA+1; float4 over o.
        #pragma unroll
        for (int p = 0; p < 8; ++p) {
            float lo[4], hi[4];
            #pragma unroll
            for (int oi = 0; oi < 4; ++oi) {
                lo[oi] = sigmoidf(__uint_as_float((unsigned)(acc[oi][p] & 0xffffffffull)) + bias[oi]);
                hi[oi] = sigmoidf(__uint_as_float((unsigned)(acc[oi][p] >> 32)) + bias[oi]);
            }
            const int nA = n0 + 2 * p, nB = nA + 1;
            #pragma unroll
            for (int half = 0; half < 2; ++half) {
                const int n = half ? nB : nA;
                if (n >= nn) continue;
                const float* v = half ? hi : lo;
                const float4 v4 = make_float4(v[0], v[1], v[2], v[3]);
                const size_t off = ((size_t)(base + n)) * HIDDEN + o0;
                if (s == 0) {
                    *reinterpret_cast<float4*>(g_S + off) = v4;
                } else {
                    *reinterpret_cast<float4*>(g_I + off) = v4;
                    const float gm = sgam[n];
                    *reinterpret_cast<float4*>(out + (size_t)2 * N_NODES * HIDDEN + off)
                        = make_float4(gm * v4.x, gm * v4.y, gm * v4.z, gm * v4.w);
                    *reinterpret_cast<float4*>(out + (size_t)3 * N_NODES * HIDDEN + off)
                        = make_float4(0.f, 0.f, 0.f, 0.f);
                }
            }
        }
        __syncthreads();  // protect xs before next s
    }
}

// ---------------------------------------------------------------------------
// K2: bin edges by destination row. slot via int atomic; overflow -> list.
// ---------------------------------------------------------------------------
__global__ __launch_bounds__(256) void k_place(
    const int* __restrict__ rows, const int* __restrict__ cols, int n_edges)
{
    const int i = blockIdx.x * 256 + threadIdx.x;
    if (i >= n_edges) return;
    int r = rows[i], c = cols[i];
    r = min(max(r, 0), N_NODES - 1);
    c = min(max(c, 0), N_NODES - 1);
    const int slot = atomicAdd(&g_cnt[r], 1);
    if (slot < CAP) {
        g_bin[(size_t)r * CAP + slot] = c;
    } else {
        const int o = atomicAdd(&g_ovf_cnt, 1);
        g_ovf[2 * o] = r;
        g_ovf[2 * o + 1] = c;
    }
}

// ---------------------------------------------------------------------------
// K3: gather + finalize. Warp per node: AI = sum_{in-edges} I[col], then
//     dS = -beta*AI*S ; dI = -dS - gamma*I. No float atomics.
// ---------------------------------------------------------------------------
__global__ __launch_bounds__(256) void k_gather_final(
    const float* __restrict__ x, float* __restrict__ out)
{
    const int node = (blockIdx.x * 256 + threadIdx.x) >> 5;
    if (node >= N_NODES) return;
    const int lane = threadIdx.x & 31;

    const int d = min(g_cnt[node], CAP);
    const int* bin = g_bin + (size_t)node * CAP;
    const float4* I4 = reinterpret_cast<const float4*>(g_I);

    float4 a = make_float4(0.f, 0.f, 0.f, 0.f);
    int i = 0;
    for (; i + 4 <= d; i += 4) {   // 4 outstanding L2 loads for MLP
        const int c0 = bin[i], c1 = bin[i + 1], c2 = bin[i + 2], c3 = bin[i + 3];
        const float4 v0 = I4[(size_t)c0 * 32 + lane];
        const float4 v1 = I4[(size_t)c1 * 32 + lane];
        const float4 v2 = I4[(size_t)c2 * 32 + lane];
        const float4 v3 = I4[(size_t)c3 * 32 + lane];
        a.x += v0.x + v1.x + v2.x + v3.x;
        a.y += v0.y + v1.y + v2.y + v3.y;
        a.z += v0.z + v1.z + v2.z + v3.z;
        a.w += v0.w + v1.w + v2.w + v3.w;
    }
    for (; i < d; ++i) {
        const float4 v = I4[(size_t)bin[i] * 32 + lane];
        a.x += v.x; a.y += v.y; a.z += v.z; a.w += v.w;
    }

    const float beta = x[((size_t)3 * N_NODES + node) * HIDDEN];
    const size_t fo = (size_t)node * 32 + lane;
    const float4 S4 = reinterpret_cast<const float4*>(g_S)[fo];
    const float4 G4 = reinterpret_cast<const float4*>(
        out + (size_t)2 * N_NODES * HIDDEN)[fo];

    float4 dS, dI;
    dS.x = -beta * a.x * S4.x;  dI.x = -dS.x - G4.x;
    dS.y = -beta * a.y * S4.y;  dI.y = -dS.y - G4.y;
    dS.z = -beta * a.z * S4.z;  dI.z = -dS.z - G4.z;
    dS.w = -beta * a.w * S4.w;  dI.w = -dS.w - G4.w;

    reinterpret_cast<float4*>(out)[fo] = dS;
    reinterpret_cast<float4*>(out + (size_t)N_NODES * HIDDEN)[fo] = dI;
}

// ---------------------------------------------------------------------------
// K4: overflow fix-up (expected empty). Adds the missing edge contributions
//     directly into dS/dI via atomics.
// ---------------------------------------------------------------------------
__global__ __launch_bounds__(256) void k_ovf(
    const float* __restrict__ x, float* __restrict__ out)
{
    const int n = g_ovf_cnt;
    if (n <= 0) return;
    const long long total = (long long)n * HIDDEN;
    for (long long idx = threadIdx.x; idx < total; idx += 256) {
        const int e = (int)(idx >> 7);
        const int j = (int)(idx & 127);
        const int r = g_ovf[2 * e];
        const int c = g_ovf[2 * e + 1];
        const float v = g_I[(size_t)c * HIDDEN + j];
        const float beta = x[((size_t)3 * N_NODES + r) * HIDDEN];
        const float delta = -beta * v * g_S[(size_t)r * HIDDEN + j];
        atomicAdd(&out[(size_t)r * HIDDEN + j], delta);
        atomicAdd(&out[(size_t)N_NODES * HIDDEN + (size_t)r * HIDDEN + j], -delta);
    }
}

// ---------------------------------------------------------------------------
extern "C" void kernel_launch(void* const* d_in, const int* in_sizes, int n_in,
                              void* d_out, int out_size)
{
    const float* x    = (const float*)d_in[0];
    const float* W    = (const float*)d_in[1];
    const float* b    = (const float*)d_in[2];
    const int*   rows = (const int*)d_in[3];
    const int*   cols = (const int*)d_in[4];
    float*       out  = (float*)d_out;

    const int n_edges = in_sizes[3];

    const size_t smem = (size_t)(128 * 132 + 128 * 130 + 128) * sizeof(float);
    cudaFuncSetAttribute(k_gemm, cudaFuncAttributeMaxDynamicSharedMemorySize,
                         (int)smem);

    const int gemm_blocks = (N_NODES + NPB - 1) / NPB;
    k_gemm<<<gemm_blocks, 256, smem>>>(x, W, b, out);

    k_place<<<(n_edges + 255) / 256, 256>>>(rows, cols, n_edges);

    const int gf_blocks = (N_NODES * 32 + 255) / 256;  // warp per node
    k_gather_final<<<gf_blocks, 256>>>(x, out);

    k_ovf<<<1, 256>>>(x, out);
}